// round 4
// baseline (speedup 1.0000x reference)
#include <cuda_runtime.h>
#include <cuda_bf16.h>
#include <cstdint>
#include <math.h>

// ---------------- problem dims ----------------
#define SEQ   512
#define BATCH 64
#define INPUT 256
#define HID   1024

// ---------------- config ----------------
#define NCTA  128            // 16 m-tiles x 8 k-slices
#define NTHR  256
#define NM    16             // m CTAs (256 gate-rows each)
#define NKS   8              // k slices (160 k each: 128 h + 32 x)
#define RPC   256            // rows per CTA (4 gates x 64 j)
#define ASTR  336            // bytes per smem row (160*2 + 16 pad)
#define OFF_AHI 0
#define OFF_ALO (RPC*ASTR)
#define OFF_BHI (2*RPC*ASTR)
#define OFF_BLO (2*RPC*ASTR + BATCH*ASTR)
#define SMEM_TOTAL (2*RPC*ASTR + 2*BATCH*ASTR) // 215040

// ---------------- scratch ----------------
__device__ __align__(16) __nv_bfloat16 g_hhi[BATCH * HID];
__device__ __align__(16) __nv_bfloat16 g_hlo[BATCH * HID];
__device__ __align__(16) __nv_bfloat16 g_xhi[(size_t)SEQ * BATCH * INPUT];
__device__ __align__(16) __nv_bfloat16 g_xlo[(size_t)SEQ * BATCH * INPUT];
__device__ float    g_part[NKS * NM * RPC * BATCH];  // [ks][m][row][b]
__device__ unsigned g_flags[NCTA * 32];              // 128B stride per CTA

struct Params {
    const float* x;
    const float* Wx[4]; const float* bx[4];
    const float* Wh[4]; const float* bh[4];
    float* out;
};

// ---------------- helpers ----------------
__device__ __forceinline__ uint32_t smem_u32(const void* p) {
    uint32_t a;
    asm("{ .reg .u64 t; cvta.to.shared.u64 t, %1; cvt.u32.u64 %0, t; }" : "=r"(a) : "l"(p));
    return a;
}
__device__ __forceinline__ void ldsm4(uint32_t* r, uint32_t addr) {
    asm volatile("ldmatrix.sync.aligned.m8n8.x4.shared.b16 {%0,%1,%2,%3}, [%4];"
        : "=r"(r[0]), "=r"(r[1]), "=r"(r[2]), "=r"(r[3]) : "r"(addr));
}
__device__ __forceinline__ void ldsm2(uint32_t* r, uint32_t addr) {
    asm volatile("ldmatrix.sync.aligned.m8n8.x2.shared.b16 {%0,%1}, [%2];"
        : "=r"(r[0]), "=r"(r[1]) : "r"(addr));
}
__device__ __forceinline__ void mma_bf16(float* d, const uint32_t* a, const uint32_t* b) {
    asm volatile(
        "mma.sync.aligned.m16n8k16.row.col.f32.bf16.bf16.f32 "
        "{%0,%1,%2,%3}, {%4,%5,%6,%7}, {%8,%9}, {%0,%1,%2,%3};"
        : "+f"(d[0]), "+f"(d[1]), "+f"(d[2]), "+f"(d[3])
        : "r"(a[0]), "r"(a[1]), "r"(a[2]), "r"(a[3]), "r"(b[0]), "r"(b[1]));
}
__device__ __forceinline__ void split2(float va, float vb, uint32_t& hi, uint32_t& lo) {
    __nv_bfloat16 ha = __float2bfloat16_rn(va);
    __nv_bfloat16 hb = __float2bfloat16_rn(vb);
    float ra = va - __bfloat162float(ha);
    float rb = vb - __bfloat162float(hb);
    __nv_bfloat162 hp; hp.x = ha; hp.y = hb;
    __nv_bfloat162 lp; lp.x = __float2bfloat16_rn(ra); lp.y = __float2bfloat16_rn(rb);
    hi = *(uint32_t*)&hp;
    lo = *(uint32_t*)&lp;
}
__device__ __forceinline__ float sigm(float x) { return 1.0f / (1.0f + __expf(-x)); }

// flag-array grid barrier: no atomic contention
__device__ __forceinline__ void grid_barrier(int cta, unsigned val) {
    __syncthreads();
    if (threadIdx.x == 0) {
        __threadfence();
        *(volatile unsigned*)&g_flags[cta * 32] = val;
    }
    if (threadIdx.x < NCTA) {
        while (*(volatile unsigned*)&g_flags[threadIdx.x * 32] < val) { }
        __threadfence();
    }
    __syncthreads();
}

// ---------------------------------------------------------------------------
__global__ void init_kernel() {
    int i = blockIdx.x * blockDim.x + threadIdx.x;   // 16384 threads
    if (i < 16384) {
        ((uint2*)g_hhi)[i] = make_uint2(0u, 0u);
        ((uint2*)g_hlo)[i] = make_uint2(0u, 0u);
    }
    if (i < NCTA * 32) g_flags[i] = 0u;
}

__global__ void xsplit_kernel(const float* __restrict__ x) {
    int i = blockIdx.x * blockDim.x + threadIdx.x;   // float4 index
    if (i < (SEQ * BATCH * INPUT) / 4) {
        float4 v = ((const float4*)x)[i];
        uint32_t h0, l0, h1, l1;
        split2(v.x, v.y, h0, l0);
        split2(v.z, v.w, h1, l1);
        ((uint2*)g_xhi)[i] = make_uint2(h0, h1);
        ((uint2*)g_xlo)[i] = make_uint2(l0, l1);
    }
}

// ---------------------------------------------------------------------------
__global__ __launch_bounds__(NTHR, 1)
void lstm_mma(Params P) {
    extern __shared__ char smem[];
    const uint32_t sb = smem_u32(smem);

    const int tid  = threadIdx.x;
    const int w    = tid >> 5;
    const int l    = tid & 31;
    const int mcta = blockIdx.x >> 3;   // 0..15
    const int ks   = blockIdx.x & 7;    // 0..7
    const int cta  = blockIdx.x;
    const int j0   = mcta * 64;

    // ---- stage weights into smem (hi/lo bf16), once per launch ----
    {
        const int r = tid;
        const int gate = r >> 6, jl = r & 63, j = j0 + jl;
        const float4* wh = (const float4*)(P.Wh[gate] + (size_t)j * HID + ks * 128);
        const float4* wx = (const float4*)(P.Wx[gate] + (size_t)j * INPUT + ks * 32);
        char* ahi = smem + OFF_AHI + r * ASTR;
        char* alo = smem + OFF_ALO + r * ASTR;
        #pragma unroll 4
        for (int f = 0; f < 40; f++) {
            float4 v = (f < 32) ? wh[f] : wx[f - 32];
            uint32_t h0, l0, h1, l1;
            split2(v.x, v.y, h0, l0);
            split2(v.z, v.w, h1, l1);
            *(uint2*)(ahi + f * 8) = make_uint2(h0, h1);
            *(uint2*)(alo + f * 8) = make_uint2(l0, l1);
        }
    }

    // ---- ldmatrix lane addresses ----
    const uint32_t a_row = (uint32_t)(w * 32 + (l & 7) + ((l >> 3) & 1) * 8);
    const uint32_t a_colb = (uint32_t)(((l >> 4) & 1) * 16);
    const uint32_t aAddrHi0 = sb + OFF_AHI + a_row * ASTR + a_colb;
    const uint32_t aAddrHi1 = aAddrHi0 + 16 * ASTR;
    const uint32_t aAddrLo0 = aAddrHi0 + (OFF_ALO - OFF_AHI);
    const uint32_t aAddrLo1 = aAddrLo0 + 16 * ASTR;
    const uint32_t b_rowb = (uint32_t)((l & 7) * ASTR);
    const uint32_t b_colb = (uint32_t)(((l >> 3) & 1) * 16);
    const uint32_t bAddrHi = sb + OFF_BHI + b_rowb + b_colb;
    const uint32_t bAddrLo = bAddrHi + (OFF_BLO - OFF_BHI);

    // ---- pointwise cell ownership: 2 cells per thread ----
    const int pb  = ks * 8 + (tid & 7);
    const int jlA = tid >> 3;
    const int jlB = jlA + 32;
    const int jA  = j0 + jlA, jB = j0 + jlB;
    float biasA[4], biasB[4];
    #pragma unroll
    for (int g = 0; g < 4; g++) {
        biasA[g] = P.bh[g][jA] + P.bx[g][jA];
        biasB[g] = P.bh[g][jB] + P.bx[g][jB];
    }
    float cA = 0.0f, cB = 0.0f;

    float* out = P.out;
    const size_t BH  = (size_t)BATCH * HID;
    const size_t SBH = (size_t)SEQ * BH;

    // staging index precompute (uint4 = 8 bf16 = 16 bytes)
    const int stb = tid >> 2;           // batch 0..63
    const int stf = tid & 3;            // phase 0..3
    const uint4* hhi_src = (const uint4*)(g_hhi + (size_t)stb * HID + ks * 128);
    const uint4* hlo_src = (const uint4*)(g_hlo + (size_t)stb * HID + ks * 128);
    char* bhi_row = smem + OFF_BHI + stb * ASTR;
    char* blo_row = smem + OFF_BLO + stb * ASTR;
    const size_t x_row_off = (size_t)stb * INPUT + ks * 32;

    float* ppart = g_part + (size_t)(ks * NM + mcta) * RPC * BATCH;

    // ---- pre-loop: stage x(0) and h(0) regions ----
    {
        const uint4* xs = (const uint4*)(g_xhi + x_row_off);
        const uint4* xl = (const uint4*)(g_xlo + x_row_off);
        *(uint4*)(bhi_row + 256 + stf * 16) = __ldcg(xs + stf);
        *(uint4*)(blo_row + 256 + stf * 16) = __ldcg(xl + stf);
        #pragma unroll
        for (int q = 0; q < 4; q++) {
            int idx = stf + q * 4;
            *(uint4*)(bhi_row + idx * 16) = __ldcg(hhi_src + idx);
            *(uint4*)(blo_row + idx * 16) = __ldcg(hlo_src + idx);
        }
    }
    __syncthreads();

    for (int t = 0; t < SEQ; t++) {
        // ---- GEMM: D[256 rows][64 b], 3-pass split bf16 ----
        float d[2][8][4];
        #pragma unroll
        for (int mt = 0; mt < 2; mt++)
            #pragma unroll
            for (int nt = 0; nt < 8; nt++)
                #pragma unroll
                for (int q = 0; q < 4; q++) d[mt][nt][q] = 0.0f;

        for (int kt = 0; kt < 10; kt++) {
            const uint32_t kb = (uint32_t)(kt * 32);
            uint32_t Ah0[4], Ah1[4], Al0[4], Al1[4];
            ldsm4(Ah0, aAddrHi0 + kb);
            ldsm4(Ah1, aAddrHi1 + kb);
            ldsm4(Al0, aAddrLo0 + kb);
            ldsm4(Al1, aAddrLo1 + kb);
            #pragma unroll
            for (int nt = 0; nt < 8; nt++) {
                uint32_t Bh[2], Bl[2];
                const uint32_t bo = (uint32_t)(nt * 8 * ASTR) + kb;
                ldsm2(Bh, bAddrHi + bo);
                ldsm2(Bl, bAddrLo + bo);
                mma_bf16(d[0][nt], Ah0, Bh);
                mma_bf16(d[1][nt], Ah1, Bh);
                mma_bf16(d[0][nt], Ah0, Bl);
                mma_bf16(d[1][nt], Ah1, Bl);
                mma_bf16(d[0][nt], Al0, Bh);
                mma_bf16(d[1][nt], Al1, Bh);
            }
        }

        // ---- store partials [row][b] ----
        {
            const int r0 = w * 32 + (l >> 2);
            const int c0 = (l & 3) * 2;
            #pragma unroll
            for (int mt = 0; mt < 2; mt++) {
                #pragma unroll
                for (int nt = 0; nt < 8; nt++) {
                    int row = r0 + mt * 16;
                    int col = nt * 8 + c0;
                    *(float2*)(ppart + (size_t)row * BATCH + col) =
                        make_float2(d[mt][nt][0], d[mt][nt][1]);
                    *(float2*)(ppart + (size_t)(row + 8) * BATCH + col) =
                        make_float2(d[mt][nt][2], d[mt][nt][3]);
                }
            }
        }

        // ---- GEMM reads of B done -> overwrite x region for t+1 (overlaps bar1) ----
        __syncthreads();
        if (t + 1 < SEQ) {
            const size_t xo = (size_t)(t + 1) * BATCH * INPUT + x_row_off;
            const uint4* xs = (const uint4*)(g_xhi + xo);
            const uint4* xl = (const uint4*)(g_xlo + xo);
            *(uint4*)(bhi_row + 256 + stf * 16) = __ldcg(xs + stf);
            *(uint4*)(blo_row + 256 + stf * 16) = __ldcg(xl + stf);
        }

        grid_barrier(cta, (unsigned)(2 * t + 1));

        // ---- reduce 8 k-slices + pointwise (2 cells) ----
        {
            float accA[4], accB[4];
            #pragma unroll
            for (int g = 0; g < 4; g++) { accA[g] = biasA[g]; accB[g] = biasB[g]; }
            #pragma unroll
            for (int g = 0; g < 4; g++) {
                #pragma unroll
                for (int s = 0; s < NKS; s++) {
                    const float* pp = g_part + (size_t)(s * NM + mcta) * RPC * BATCH + pb;
                    accA[g] += __ldcg(pp + (size_t)(g * 64 + jlA) * BATCH);
                    accB[g] += __ldcg(pp + (size_t)(g * 64 + jlB) * BATCH);
                }
            }
            float f, i1, i2, o, hv;

            f = sigm(accA[0]); i1 = sigm(accA[1]); i2 = tanhf(accA[2]); o = sigm(accA[3]);
            cA = cA * f + i1 * i2;
            hv = tanhf(cA) * o;
            out[(size_t)t * BH + (size_t)pb * HID + jA] = hv;
            {
                __nv_bfloat16 hb = __float2bfloat16_rn(hv);
                g_hhi[(size_t)pb * HID + jA] = hb;
                g_hlo[(size_t)pb * HID + jA] = __float2bfloat16_rn(hv - __bfloat162float(hb));
            }
            if (t == SEQ - 1) {
                out[SBH + (size_t)pb * HID + jA] = hv;
                out[SBH + BH + (size_t)pb * HID + jA] = cA;
            }

            f = sigm(accB[0]); i1 = sigm(accB[1]); i2 = tanhf(accB[2]); o = sigm(accB[3]);
            cB = cB * f + i1 * i2;
            hv = tanhf(cB) * o;
            out[(size_t)t * BH + (size_t)pb * HID + jB] = hv;
            {
                __nv_bfloat16 hb = __float2bfloat16_rn(hv);
                g_hhi[(size_t)pb * HID + jB] = hb;
                g_hlo[(size_t)pb * HID + jB] = __float2bfloat16_rn(hv - __bfloat162float(hb));
            }
            if (t == SEQ - 1) {
                out[SBH + (size_t)pb * HID + jB] = hv;
                out[SBH + BH + (size_t)pb * HID + jB] = cB;
            }
        }

        grid_barrier(cta, (unsigned)(2 * t + 2));

        // ---- stage h region for t+1 (plain uint4 copies) ----
        if (t + 1 < SEQ) {
            #pragma unroll
            for (int q = 0; q < 4; q++) {
                int idx = stf + q * 4;
                *(uint4*)(bhi_row + idx * 16) = __ldcg(hhi_src + idx);
                *(uint4*)(blo_row + idx * 16) = __ldcg(hlo_src + idx);
            }
            __syncthreads();
        }
    }
}

// ---------------------------------------------------------------------------
extern "C" void kernel_launch(void* const* d_in, const int* in_sizes, int n_in,
                              void* d_out, int out_size) {
    Params P;
    P.x = (const float*)d_in[0];
    P.Wx[0] = (const float*)d_in[1];  P.bx[0] = (const float*)d_in[2];
    P.Wx[1] = (const float*)d_in[3];  P.bx[1] = (const float*)d_in[4];
    P.Wx[2] = (const float*)d_in[5];  P.bx[2] = (const float*)d_in[6];
    P.Wx[3] = (const float*)d_in[7];  P.bx[3] = (const float*)d_in[8];
    P.Wh[0] = (const float*)d_in[9];  P.bh[0] = (const float*)d_in[10];
    P.Wh[1] = (const float*)d_in[11]; P.bh[1] = (const float*)d_in[12];
    P.Wh[2] = (const float*)d_in[13]; P.bh[2] = (const float*)d_in[14];
    P.Wh[3] = (const float*)d_in[15]; P.bh[3] = (const float*)d_in[16];
    P.out   = (float*)d_out;

    static bool attr_set = false;
    if (!attr_set) {
        cudaFuncSetAttribute(lstm_mma, cudaFuncAttributeMaxDynamicSharedMemorySize,
                             SMEM_TOTAL);
        attr_set = true;
    }

    init_kernel<<<64, 256>>>();
    xsplit_kernel<<<(SEQ * BATCH * INPUT / 4 + 255) / 256, 256>>>(P.x);
    lstm_mma<<<NCTA, NTHR, SMEM_TOTAL>>>(P);
}